// round 14
// baseline (speedup 1.0000x reference)
#include <cuda_runtime.h>
#include <cstdint>

#define Dn 4
#define Cn 64
#define Hn 64
#define Wn 64
#define Nn 4096
#define QKn 32
#define B1 20.0f
#define B2 8.0f
#define SPL 4
#define MCH (Nn / SPL)

__device__ __align__(16) float g_qt[Dn * Nn * QKn];   // q: [d][n][32]
__device__ __align__(16) float g_kt[Dn * Nn * QKn];   // k: [d][m][32]
__device__ __align__(16) float g_part[(size_t)SPL * Dn * Nn * Cn];
__device__ float g_sump[SPL * Dn * Nn];
__device__ float g_s2p [SPL * Dn * Nn];

__device__ __forceinline__ uint32_t cvt_tf32(float f) {
    uint32_t u;
    asm("cvt.rna.tf32.f32 %0, %1;" : "=r"(u) : "f"(f));
    return u;
}
__device__ __forceinline__ uint32_t bf16pair(float lo, float hi) {
    uint32_t r;
    asm("cvt.rn.bf16x2.f32 %0, %1, %2;" : "=r"(r) : "f"(hi), "f"(lo));
    return r;
}
__device__ __forceinline__ void mma8(float4& d,
    uint32_t a0, uint32_t a1, uint32_t a2, uint32_t a3,
    uint32_t b0, uint32_t b1)
{
    asm("mma.sync.aligned.m16n8k8.row.col.f32.tf32.tf32.f32 "
        "{%0,%1,%2,%3},{%4,%5,%6,%7},{%8,%9},{%0,%1,%2,%3};"
        : "+f"(d.x), "+f"(d.y), "+f"(d.z), "+f"(d.w)
        : "r"(a0), "r"(a1), "r"(a2), "r"(a3), "r"(b0), "r"(b1));
}
__device__ __forceinline__ void mma16(float4& d,
    uint32_t a0, uint32_t a1, uint32_t a2, uint32_t a3,
    uint32_t b0, uint32_t b1)
{
    asm("mma.sync.aligned.m16n8k16.row.col.f32.bf16.bf16.f32 "
        "{%0,%1,%2,%3},{%4,%5,%6,%7},{%8,%9},{%0,%1,%2,%3};"
        : "+f"(d.x), "+f"(d.y), "+f"(d.z), "+f"(d.w)
        : "r"(a0), "r"(a1), "r"(a2), "r"(a3), "r"(b0), "r"(b1));
}

// ========================= K1: conv3x3 -> q^T, k^T (R13 proven) =========================
__global__ __launch_bounds__(256) void conv_qk(
    const float* __restrict__ x,
    const float* __restrict__ qw, const float* __restrict__ qb,
    const float* __restrict__ kw, const float* __restrict__ kb)
{
    __shared__ float xs[3][16][72];
    __shared__ float wsm[16][9][32];
    const int h = blockIdx.x, d = blockIdx.y, proj = blockIdx.z;
    const int tid = threadIdx.x, oc = tid & 31, wg = tid >> 5;
    const float* wsrc = proj ? kw : qw;
    float acc[8];
    float bia = proj ? kb[oc] : qb[oc];
#pragma unroll
    for (int j = 0; j < 8; j++) acc[j] = bia;

    for (int chunk = 0; chunk < 4; chunk++) {
        for (int i = tid; i < 16 * 64; i += 256) {
            int icl = i >> 6, w = i & 63;
            const float* xp = x + ((size_t)(d * Cn + chunk * 16 + icl)) * (Hn * Wn);
#pragma unroll
            for (int dy = 0; dy < 3; dy++) {
                int hh = h + dy - 1;
                xs[dy][icl][w + 1] = (hh >= 0 && hh < Hn) ? xp[hh * Wn + w] : 0.f;
            }
            if (w == 0)
#pragma unroll
                for (int dy = 0; dy < 3; dy++) { xs[dy][icl][0] = 0.f; xs[dy][icl][65] = 0.f; }
        }
        for (int i = tid; i < 16 * 9 * 32; i += 256) {
            int icl = i / 288, rem = i % 288;
            wsm[icl][rem >> 5][rem & 31] = wsrc[((rem & 31) * Cn + chunk * 16 + icl) * 9 + (rem >> 5)];
        }
        __syncthreads();
        for (int icl = 0; icl < 16; icl++) {
#pragma unroll
            for (int dy = 0; dy < 3; dy++) {
                float4 x0 = *(const float4*)&xs[dy][icl][wg * 8];
                float4 x1 = *(const float4*)&xs[dy][icl][wg * 8 + 4];
                float2 x2 = *(const float2*)&xs[dy][icl][wg * 8 + 8];
                float xv[10] = {x0.x, x0.y, x0.z, x0.w, x1.x, x1.y, x1.z, x1.w, x2.x, x2.y};
#pragma unroll
                for (int dx = 0; dx < 3; dx++) {
                    float wv = wsm[icl][dy * 3 + dx][oc];
#pragma unroll
                    for (int j = 0; j < 8; j++) acc[j] = fmaf(wv, xv[dx + j], acc[j]);
                }
            }
        }
        __syncthreads();
    }
    const int n = h * Wn + wg * 8;
    float* dst = proj ? g_kt : g_qt;
#pragma unroll
    for (int j = 0; j < 8; j++) dst[((size_t)(d * Nn + n + j)) * QKn + oc] = acc[j];
}

// ========================= K2: softmax1 sums only (R13 proven) =========================
__global__ __launch_bounds__(256) void qk_sums()
{
    __shared__ uint32_t qs[64 * 36];
    __shared__ uint32_t ks[128 * 36];
    __shared__ float s1w[4][64];

    const int d = blockIdx.y, gn0 = blockIdx.x * 64, gz = blockIdx.z;
    const int tid = threadIdx.x, lane = tid & 31, warp = tid >> 5;
    const int wn = warp >> 2, wm = warp & 3;
    const int g = lane >> 2, t = lane & 3;

    {
        int n = tid >> 2, cq = (tid & 3) * 8;
        const float* qp = g_qt + ((size_t)(d * Nn + gn0 + n)) * QKn + cq;
#pragma unroll
        for (int e = 0; e < 8; e++) qs[n * 36 + cq + e] = cvt_tf32(qp[e]);
    }
    __syncthreads();

    uint32_t af[2][4][4];
#pragma unroll
    for (int nt = 0; nt < 2; nt++)
#pragma unroll
        for (int kk = 0; kk < 4; kk++) {
            int r = wn * 32 + nt * 16 + g;
            af[nt][kk][0] = qs[r * 36 + kk * 8 + t];
            af[nt][kk][1] = qs[(r + 8) * 36 + kk * 8 + t];
            af[nt][kk][2] = qs[r * 36 + kk * 8 + t + 4];
            af[nt][kk][3] = qs[(r + 8) * 36 + kk * 8 + t + 4];
        }

    float part[4] = {0.f, 0.f, 0.f, 0.f};

    for (int m0 = gz * MCH; m0 < (gz + 1) * MCH; m0 += 128) {
        __syncthreads();
#pragma unroll
        for (int it = 0; it < 2; it++) {
            int gg = tid + 256 * it;
            int m = gg >> 2, cq = (gg & 3) * 8;
            const float* kp = g_kt + ((size_t)(d * Nn + m0 + m)) * QKn + cq;
#pragma unroll
            for (int e = 0; e < 8; e++) ks[m * 36 + cq + e] = cvt_tf32(kp[e]);
        }
        __syncthreads();

        float4 acc[2][4];
#pragma unroll
        for (int nt = 0; nt < 2; nt++)
#pragma unroll
            for (int mt = 0; mt < 4; mt++) acc[nt][mt] = make_float4(0.f, 0.f, 0.f, 0.f);

#pragma unroll
        for (int kk = 0; kk < 4; kk++) {
            uint32_t bf[4][2];
#pragma unroll
            for (int mt = 0; mt < 4; mt++) {
                int mr = wm * 32 + mt * 8 + g;
                bf[mt][0] = ks[mr * 36 + kk * 8 + t];
                bf[mt][1] = ks[mr * 36 + kk * 8 + t + 4];
            }
#pragma unroll
            for (int nt = 0; nt < 2; nt++)
#pragma unroll
                for (int mt = 0; mt < 4; mt++)
                    mma8(acc[nt][mt], af[nt][kk][0], af[nt][kk][1], af[nt][kk][2], af[nt][kk][3],
                         bf[mt][0], bf[mt][1]);
        }

#pragma unroll
        for (int nt = 0; nt < 2; nt++)
#pragma unroll
            for (int mt = 0; mt < 4; mt++) {
                float4 c = acc[nt][mt];
                part[nt * 2 + 0] += __expf(c.x - B1) + __expf(c.y - B1);
                part[nt * 2 + 1] += __expf(c.z - B1) + __expf(c.w - B1);
            }
    }

#pragma unroll
    for (int o = 1; o < 4; o <<= 1)
#pragma unroll
        for (int i = 0; i < 4; i++) part[i] += __shfl_xor_sync(0xffffffffu, part[i], o);
    if (t == 0)
#pragma unroll
        for (int i = 0; i < 4; i++)
            s1w[wm][wn * 32 + (i >> 1) * 16 + (i & 1) * 8 + g] = part[i];
    __syncthreads();
    if (tid < 64)
        g_sump[(gz * Dn + d) * Nn + gn0 + tid] =
            s1w[0][tid] + s1w[1][tid] + s1w[2][tid] + s1w[3][tid];
}

// ========================= K3: fused scores(tf32) + double softmax + attn@V(bf16) =========================
__global__ __launch_bounds__(256) void attn_v(
    const float* __restrict__ x, const float* __restrict__ atten)
{
    extern __shared__ float sh[];
    uint32_t* qs = (uint32_t*)sh;               // [128][36] tf32
    uint32_t* ks = qs + 128 * 36;               // [64][36]  tf32
    uint32_t* es = ks + 64 * 36;                // [128][36] bf16x2 pairs
    uint32_t* vs = es + 128 * 36;               // [64][36]  bf16x2 pairs
    float* is1 = (float*)(vs + 64 * 36);        // [128]
    float* s2w = is1 + 128;                     // [2][128]

    const int d = blockIdx.y, gn0 = blockIdx.x * 128, gz = blockIdx.z;
    const int tid = threadIdx.x, lane = tid & 31, warp = tid >> 5;
    const int wn = warp >> 1, wm = warp & 1;
    const int g = lane >> 2, t = lane & 3;

    if (tid < 128) {
        float s = 0.f;
#pragma unroll
        for (int p = 0; p < SPL; p++) s += g_sump[(p * Dn + d) * Nn + gn0 + tid];
        is1[tid] = 1.0f / s;
    }
#pragma unroll
    for (int it = 0; it < 2; it++) {
        int gg = tid + 256 * it;
        int n = gg >> 2, cq = (gg & 3) * 8;
        const float* qp = g_qt + ((size_t)(d * Nn + gn0 + n)) * QKn + cq;
#pragma unroll
        for (int e = 0; e < 8; e++) qs[n * 36 + cq + e] = cvt_tf32(qp[e]);
    }

    float4 acc[2][4];
#pragma unroll
    for (int nt = 0; nt < 2; nt++)
#pragma unroll
        for (int ct = 0; ct < 4; ct++) acc[nt][ct] = make_float4(0.f, 0.f, 0.f, 0.f);
    float part2[2][2] = {{0.f, 0.f}, {0.f, 0.f}};

    for (int m0 = gz * MCH; m0 < (gz + 1) * MCH; m0 += 64) {
        __syncthreads();
        {
            int m = tid >> 2, cq = (tid & 3) * 8;
            const float* kp = g_kt + ((size_t)(d * Nn + m0 + m)) * QKn + cq;
#pragma unroll
            for (int e = 0; e < 8; e++) ks[m * 36 + cq + e] = cvt_tf32(kp[e]);
        }
        // stage v 64c x 64m as bf16 pairs
#pragma unroll
        for (int it = 0; it < 4; it++) {
            int gg = tid + 256 * it;
            int c = gg >> 4, mq = gg & 15;
            float4 v4 = *(const float4*)(x + ((size_t)(d * Cn + c)) * Nn + m0 + mq * 4);
            uint2 pk = make_uint2(bf16pair(v4.x, v4.y), bf16pair(v4.z, v4.w));
            *(uint2*)&vs[c * 36 + mq * 2] = pk;
        }
        __syncthreads();

        // --- score mma: 128n x 64m, warp tile 32n x 32m (tf32) ---
        float4 sacc[2][4];
#pragma unroll
        for (int nt = 0; nt < 2; nt++)
#pragma unroll
            for (int mt = 0; mt < 4; mt++) sacc[nt][mt] = make_float4(0.f, 0.f, 0.f, 0.f);
#pragma unroll
        for (int kk = 0; kk < 4; kk++) {
            uint32_t a[2][4], b[4][2];
#pragma unroll
            for (int nt = 0; nt < 2; nt++) {
                int r = wn * 32 + nt * 16 + g;
                a[nt][0] = qs[r * 36 + kk * 8 + t];
                a[nt][1] = qs[(r + 8) * 36 + kk * 8 + t];
                a[nt][2] = qs[r * 36 + kk * 8 + t + 4];
                a[nt][3] = qs[(r + 8) * 36 + kk * 8 + t + 4];
            }
#pragma unroll
            for (int mt = 0; mt < 4; mt++) {
                int mr = wm * 32 + mt * 8 + g;
                b[mt][0] = ks[mr * 36 + kk * 8 + t];
                b[mt][1] = ks[mr * 36 + kk * 8 + t + 4];
            }
#pragma unroll
            for (int nt = 0; nt < 2; nt++)
#pragma unroll
                for (int mt = 0; mt < 4; mt++)
                    mma8(sacc[nt][mt], a[nt][0], a[nt][1], a[nt][2], a[nt][3],
                         b[mt][0], b[mt][1]);
        }

        // --- e = exp(exp(s-B1)*is1 + atten - B2) -> es (bf16x2); sum2 partials ---
#pragma unroll
        for (int nt = 0; nt < 2; nt++)
#pragma unroll
            for (int mt = 0; mt < 4; mt++) {
                float4 c = sacc[nt][mt];
                int rl = wn * 32 + nt * 16 + g;
                int ml = wm * 32 + mt * 8 + 2 * t;
                size_t gb = ((size_t)(d * Nn + gn0 + rl)) * Nn + m0 + ml;
                float2 a0 = *(const float2*)(atten + gb);
                float2 a1 = *(const float2*)(atten + gb + (size_t)8 * Nn);
                float i0 = is1[rl], i1 = is1[rl + 8];
                float e0 = __expf(fmaf(__expf(c.x - B1), i0, a0.x) - B2);
                float e1 = __expf(fmaf(__expf(c.y - B1), i0, a0.y) - B2);
                float e2 = __expf(fmaf(__expf(c.z - B1), i1, a1.x) - B2);
                float e3 = __expf(fmaf(__expf(c.w - B1), i1, a1.y) - B2);
                part2[nt][0] += e0 + e1;
                part2[nt][1] += e2 + e3;
                int pc = wm * 16 + mt * 4 + t;   // m-pair column
                es[rl * 36 + pc]       = bf16pair(e0, e1);
                es[(rl + 8) * 36 + pc] = bf16pair(e2, e3);
            }
        __syncthreads();

        // --- ev mma: 128n x 64c, warp tile 32n x 32c, k=64m (bf16, 4 k-steps) ---
#pragma unroll
        for (int kk = 0; kk < 4; kk++) {
            uint32_t a[2][4], b[4][2];
#pragma unroll
            for (int nt = 0; nt < 2; nt++) {
                int r = wn * 32 + nt * 16 + g;
                a[nt][0] = es[r * 36 + kk * 8 + t];
                a[nt][1] = es[(r + 8) * 36 + kk * 8 + t];
                a[nt][2] = es[r * 36 + kk * 8 + t + 4];
                a[nt][3] = es[(r + 8) * 36 + kk * 8 + t + 4];
            }
#pragma unroll
            for (int ct = 0; ct < 4; ct++) {
                int cr = wm * 32 + ct * 8 + g;
                b[ct][0] = vs[cr * 36 + kk * 8 + t];
                b[ct][1] = vs[cr * 36 + kk * 8 + t + 4];
            }
#pragma unroll
            for (int nt = 0; nt < 2; nt++)
#pragma unroll
                for (int ct = 0; ct < 4; ct++)
                    mma16(acc[nt][ct], a[nt][0], a[nt][1], a[nt][2], a[nt][3],
                          b[ct][0], b[ct][1]);
        }
    }

#pragma unroll
    for (int o = 1; o < 4; o <<= 1) {
#pragma unroll
        for (int nt = 0; nt < 2; nt++) {
            part2[nt][0] += __shfl_xor_sync(0xffffffffu, part2[nt][0], o);
            part2[nt][1] += __shfl_xor_sync(0xffffffffu, part2[nt][1], o);
        }
    }
    if (t == 0) {
#pragma unroll
        for (int nt = 0; nt < 2; nt++) {
            s2w[wm * 128 + wn * 32 + nt * 16 + g]     = part2[nt][0];
            s2w[wm * 128 + wn * 32 + nt * 16 + 8 + g] = part2[nt][1];
        }
    }
    __syncthreads();
    if (tid < 128)
        g_s2p[(gz * Dn + d) * Nn + gn0 + tid] = s2w[tid] + s2w[128 + tid];

#pragma unroll
    for (int nt = 0; nt < 2; nt++)
#pragma unroll
        for (int ct = 0; ct < 4; ct++) {
            float4 c = acc[nt][ct];
            int row = gn0 + wn * 32 + nt * 16 + g;
            int col = wm * 32 + ct * 8 + 2 * t;
            size_t b = ((size_t)((gz * Dn + d) * Nn) + row) * Cn + col;
            *(float2*)(g_part + b)          = make_float2(c.x, c.y);
            *(float2*)(g_part + b + 8 * Cn) = make_float2(c.z, c.w);
        }
}

// ========================= K4: reduce partials + normalize + residual =========================
__global__ __launch_bounds__(256) void epilogue(
    const float* __restrict__ x, const float* __restrict__ gamma,
    float* __restrict__ out)
{
    __shared__ float tb[32][33];
    __shared__ float inv[32];
    const int n0 = blockIdx.x * 32, c0 = blockIdx.y * 32, d = blockIdx.z;
    const int i = threadIdx.x & 31, j = threadIdx.x >> 5;
    const float g = gamma[0];

    if (threadIdx.x < 32) {
        float s = 0.f;
#pragma unroll
        for (int p = 0; p < SPL; p++) s += g_s2p[(p * Dn + d) * Nn + n0 + threadIdx.x];
        inv[threadIdx.x] = g / s;
    }
#pragma unroll
    for (int r = 0; r < 32; r += 8) {
        size_t base = ((size_t)(d * Nn) + n0 + j + r) * Cn + c0 + i;
        float v = 0.f;
#pragma unroll
        for (int p = 0; p < SPL; p++) v += g_part[(size_t)p * Dn * Nn * Cn + base];
        tb[j + r][i] = v;
    }
    __syncthreads();
#pragma unroll
    for (int r = 0; r < 32; r += 8) {
        size_t idx = ((size_t)(d * Cn + c0 + j + r)) * Nn + n0 + i;
        out[idx] = fmaf(tb[i][j + r], inv[i], x[idx]);
    }
}

// ============================================================================
extern "C" void kernel_launch(void* const* d_in, const int* in_sizes, int n_in,
                              void* d_out, int out_size)
{
    const float* x   = (const float*)d_in[0];
    const float* att = (const float*)d_in[1];
    const float* qw  = (const float*)d_in[2];
    const float* qb  = (const float*)d_in[3];
    const float* kw  = (const float*)d_in[4];
    const float* kb  = (const float*)d_in[5];
    const float* gm  = (const float*)d_in[6];
    float* out = (float*)d_out;

    static int smem_set = 0;
    const int dyn = (128 * 36 + 64 * 36 + 128 * 36 + 64 * 36 + 128 + 256) * 4;
    if (!smem_set) {
        cudaFuncSetAttribute(attn_v, cudaFuncAttributeMaxDynamicSharedMemorySize, dyn);
        smem_set = 1;
    }

    conv_qk <<<dim3(Hn, Dn, 2), 256>>>(x, qw, qb, kw, kb);
    qk_sums <<<dim3(Nn / 64, Dn, SPL), 256>>>();
    attn_v  <<<dim3(Nn / 128, Dn, SPL), 256, dyn>>>(x, att);
    epilogue<<<dim3(Nn / 32, Cn / 32, Dn), 256>>>(x, gm, out);
}

// round 15
// speedup vs baseline: 1.2164x; 1.2164x over previous
#include <cuda_runtime.h>
#include <cstdint>

#define Dn 4
#define Cn 64
#define Hn 64
#define Wn 64
#define Nn 4096
#define QKn 32
#define B1 20.0f
#define B2 8.0f
#define SPL 4
#define MCH (Nn / SPL)

__device__ __align__(16) float g_qt[Dn * Nn * QKn];   // q: [d][n][32]
__device__ __align__(16) float g_kt[Dn * Nn * QKn];   // k: [d][m][32]
__device__ __align__(16) float g_part[(size_t)SPL * Dn * Nn * Cn];
__device__ float g_sump[SPL * Dn * Nn];
__device__ float g_s2p [SPL * Dn * Nn];

__device__ __forceinline__ uint32_t cvt_tf32(float f) {
    uint32_t u;
    asm("cvt.rna.tf32.f32 %0, %1;" : "=r"(u) : "f"(f));
    return u;
}
__device__ __forceinline__ void mma8(float4& d,
    uint32_t a0, uint32_t a1, uint32_t a2, uint32_t a3,
    uint32_t b0, uint32_t b1)
{
    asm("mma.sync.aligned.m16n8k8.row.col.f32.tf32.tf32.f32 "
        "{%0,%1,%2,%3},{%4,%5,%6,%7},{%8,%9},{%0,%1,%2,%3};"
        : "+f"(d.x), "+f"(d.y), "+f"(d.z), "+f"(d.w)
        : "r"(a0), "r"(a1), "r"(a2), "r"(a3), "r"(b0), "r"(b1));
}

// ========================= K0: zero q/k accumulators =========================
__global__ __launch_bounds__(256) void zero_qk()
{
    int i = blockIdx.x * 256 + threadIdx.x;
    ((float4*)g_qt)[i] = make_float4(0.f, 0.f, 0.f, 0.f);
    ((float4*)g_kt)[i] = make_float4(0.f, 0.f, 0.f, 0.f);
}

// ========================= K1: conv3x3 -> q^T, k^T =========================
// grid (H, D, 4): z = proj*2 + ichalf. Each block does 2 ic-chunks, RED-adds.
__global__ __launch_bounds__(256) void conv_qk(
    const float* __restrict__ x,
    const float* __restrict__ qw, const float* __restrict__ qb,
    const float* __restrict__ kw, const float* __restrict__ kb)
{
    __shared__ float xs[3][16][72];
    __shared__ float wsm[16][9][32];
    const int h = blockIdx.x, d = blockIdx.y;
    const int proj = blockIdx.z >> 1, ichalf = blockIdx.z & 1;
    const int tid = threadIdx.x, oc = tid & 31, wg = tid >> 5;
    const float* wsrc = proj ? kw : qw;
    float acc[8];
    float bia = (ichalf == 0) ? (proj ? kb[oc] : qb[oc]) : 0.f;
#pragma unroll
    for (int j = 0; j < 8; j++) acc[j] = bia;

    for (int ch = 0; ch < 2; ch++) {
        const int chunk = ichalf * 2 + ch;
        for (int i = tid; i < 16 * 64; i += 256) {
            int icl = i >> 6, w = i & 63;
            const float* xp = x + ((size_t)(d * Cn + chunk * 16 + icl)) * (Hn * Wn);
#pragma unroll
            for (int dy = 0; dy < 3; dy++) {
                int hh = h + dy - 1;
                xs[dy][icl][w + 1] = (hh >= 0 && hh < Hn) ? xp[hh * Wn + w] : 0.f;
            }
            if (w == 0)
#pragma unroll
                for (int dy = 0; dy < 3; dy++) { xs[dy][icl][0] = 0.f; xs[dy][icl][65] = 0.f; }
        }
        for (int i = tid; i < 16 * 9 * 32; i += 256) {
            int icl = i / 288, rem = i % 288;
            wsm[icl][rem >> 5][rem & 31] = wsrc[((rem & 31) * Cn + chunk * 16 + icl) * 9 + (rem >> 5)];
        }
        __syncthreads();
        for (int icl = 0; icl < 16; icl++) {
#pragma unroll
            for (int dy = 0; dy < 3; dy++) {
                float4 x0 = *(const float4*)&xs[dy][icl][wg * 8];
                float4 x1 = *(const float4*)&xs[dy][icl][wg * 8 + 4];
                float2 x2 = *(const float2*)&xs[dy][icl][wg * 8 + 8];
                float xv[10] = {x0.x, x0.y, x0.z, x0.w, x1.x, x1.y, x1.z, x1.w, x2.x, x2.y};
#pragma unroll
                for (int dx = 0; dx < 3; dx++) {
                    float wv = wsm[icl][dy * 3 + dx][oc];
#pragma unroll
                    for (int j = 0; j < 8; j++) acc[j] = fmaf(wv, xv[dx + j], acc[j]);
                }
            }
        }
        __syncthreads();
    }
    const int n = h * Wn + wg * 8;
    float* dst = proj ? g_kt : g_qt;
#pragma unroll
    for (int j = 0; j < 8; j++)
        atomicAdd(&dst[((size_t)(d * Nn + n + j)) * QKn + oc], acc[j]);
}

// ========================= K2: softmax1 sums only (R13 proven) =========================
__global__ __launch_bounds__(256) void qk_sums()
{
    __shared__ uint32_t qs[64 * 36];
    __shared__ uint32_t ks[128 * 36];
    __shared__ float s1w[4][64];

    const int d = blockIdx.y, gn0 = blockIdx.x * 64, gz = blockIdx.z;
    const int tid = threadIdx.x, lane = tid & 31, warp = tid >> 5;
    const int wn = warp >> 2, wm = warp & 3;
    const int g = lane >> 2, t = lane & 3;

    {
        int n = tid >> 2, cq = (tid & 3) * 8;
        const float* qp = g_qt + ((size_t)(d * Nn + gn0 + n)) * QKn + cq;
#pragma unroll
        for (int e = 0; e < 8; e++) qs[n * 36 + cq + e] = cvt_tf32(qp[e]);
    }
    __syncthreads();

    uint32_t af[2][4][4];
#pragma unroll
    for (int nt = 0; nt < 2; nt++)
#pragma unroll
        for (int kk = 0; kk < 4; kk++) {
            int r = wn * 32 + nt * 16 + g;
            af[nt][kk][0] = qs[r * 36 + kk * 8 + t];
            af[nt][kk][1] = qs[(r + 8) * 36 + kk * 8 + t];
            af[nt][kk][2] = qs[r * 36 + kk * 8 + t + 4];
            af[nt][kk][3] = qs[(r + 8) * 36 + kk * 8 + t + 4];
        }

    float part[4] = {0.f, 0.f, 0.f, 0.f};

    for (int m0 = gz * MCH; m0 < (gz + 1) * MCH; m0 += 128) {
        __syncthreads();
#pragma unroll
        for (int it = 0; it < 2; it++) {
            int gg = tid + 256 * it;
            int m = gg >> 2, cq = (gg & 3) * 8;
            const float* kp = g_kt + ((size_t)(d * Nn + m0 + m)) * QKn + cq;
#pragma unroll
            for (int e = 0; e < 8; e++) ks[m * 36 + cq + e] = cvt_tf32(kp[e]);
        }
        __syncthreads();

        float4 acc[2][4];
#pragma unroll
        for (int nt = 0; nt < 2; nt++)
#pragma unroll
            for (int mt = 0; mt < 4; mt++) acc[nt][mt] = make_float4(0.f, 0.f, 0.f, 0.f);

#pragma unroll
        for (int kk = 0; kk < 4; kk++) {
            uint32_t bf[4][2];
#pragma unroll
            for (int mt = 0; mt < 4; mt++) {
                int mr = wm * 32 + mt * 8 + g;
                bf[mt][0] = ks[mr * 36 + kk * 8 + t];
                bf[mt][1] = ks[mr * 36 + kk * 8 + t + 4];
            }
#pragma unroll
            for (int nt = 0; nt < 2; nt++)
#pragma unroll
                for (int mt = 0; mt < 4; mt++)
                    mma8(acc[nt][mt], af[nt][kk][0], af[nt][kk][1], af[nt][kk][2], af[nt][kk][3],
                         bf[mt][0], bf[mt][1]);
        }

#pragma unroll
        for (int nt = 0; nt < 2; nt++)
#pragma unroll
            for (int mt = 0; mt < 4; mt++) {
                float4 c = acc[nt][mt];
                part[nt * 2 + 0] += __expf(c.x - B1) + __expf(c.y - B1);
                part[nt * 2 + 1] += __expf(c.z - B1) + __expf(c.w - B1);
            }
    }

#pragma unroll
    for (int o = 1; o < 4; o <<= 1)
#pragma unroll
        for (int i = 0; i < 4; i++) part[i] += __shfl_xor_sync(0xffffffffu, part[i], o);
    if (t == 0)
#pragma unroll
        for (int i = 0; i < 4; i++)
            s1w[wm][wn * 32 + (i >> 1) * 16 + (i & 1) * 8 + g] = part[i];
    __syncthreads();
    if (tid < 64)
        g_sump[(gz * Dn + d) * Nn + gn0 + tid] =
            s1w[0][tid] + s1w[1][tid] + s1w[2][tid] + s1w[3][tid];
}

// ========================= K3: fused scores + double softmax + attn@V (R13 proven) =========================
__global__ __launch_bounds__(256) void attn_v(
    const float* __restrict__ x, const float* __restrict__ atten)
{
    extern __shared__ float sh[];
    uint32_t* qs = (uint32_t*)sh;               // [128][36]
    uint32_t* ks = qs + 128 * 36;               // [64][36]
    uint32_t* es = ks + 64 * 36;                // [128][68]
    uint32_t* vs = es + 128 * 68;               // [64][68]
    float* is1 = (float*)(vs + 64 * 68);        // [128]
    float* s2w = is1 + 128;                     // [2][128]

    const int d = blockIdx.y, gn0 = blockIdx.x * 128, gz = blockIdx.z;
    const int tid = threadIdx.x, lane = tid & 31, warp = tid >> 5;
    const int wn = warp >> 1, wm = warp & 1;
    const int g = lane >> 2, t = lane & 3;

    if (tid < 128) {
        float s = 0.f;
#pragma unroll
        for (int p = 0; p < SPL; p++) s += g_sump[(p * Dn + d) * Nn + gn0 + tid];
        is1[tid] = 1.0f / s;
    }
#pragma unroll
    for (int it = 0; it < 2; it++) {
        int gg = tid + 256 * it;
        int n = gg >> 2, cq = (gg & 3) * 8;
        const float* qp = g_qt + ((size_t)(d * Nn + gn0 + n)) * QKn + cq;
#pragma unroll
        for (int e = 0; e < 8; e++) qs[n * 36 + cq + e] = cvt_tf32(qp[e]);
    }

    float4 acc[2][4];
#pragma unroll
    for (int nt = 0; nt < 2; nt++)
#pragma unroll
        for (int ct = 0; ct < 4; ct++) acc[nt][ct] = make_float4(0.f, 0.f, 0.f, 0.f);
    float part2[2][2] = {{0.f, 0.f}, {0.f, 0.f}};

    for (int m0 = gz * MCH; m0 < (gz + 1) * MCH; m0 += 64) {
        __syncthreads();
        {
            int m = tid >> 2, cq = (tid & 3) * 8;
            const float* kp = g_kt + ((size_t)(d * Nn + m0 + m)) * QKn + cq;
#pragma unroll
            for (int e = 0; e < 8; e++) ks[m * 36 + cq + e] = cvt_tf32(kp[e]);
        }
#pragma unroll
        for (int it = 0; it < 4; it++) {
            int gg = tid + 256 * it;
            int c = gg >> 4, mq = gg & 15;
            float4 v4 = *(const float4*)(x + ((size_t)(d * Cn + c)) * Nn + m0 + mq * 4);
            *(uint4*)&vs[c * 68 + mq * 4] =
                make_uint4(cvt_tf32(v4.x), cvt_tf32(v4.y), cvt_tf32(v4.z), cvt_tf32(v4.w));
        }
        __syncthreads();

        // --- score mma: 128n x 64m, warp tile 32n x 32m ---
        float4 sacc[2][4];
#pragma unroll
        for (int nt = 0; nt < 2; nt++)
#pragma unroll
            for (int mt = 0; mt < 4; mt++) sacc[nt][mt] = make_float4(0.f, 0.f, 0.f, 0.f);
#pragma unroll
        for (int kk = 0; kk < 4; kk++) {
            uint32_t a[2][4], b[4][2];
#pragma unroll
            for (int nt = 0; nt < 2; nt++) {
                int r = wn * 32 + nt * 16 + g;
                a[nt][0] = qs[r * 36 + kk * 8 + t];
                a[nt][1] = qs[(r + 8) * 36 + kk * 8 + t];
                a[nt][2] = qs[r * 36 + kk * 8 + t + 4];
                a[nt][3] = qs[(r + 8) * 36 + kk * 8 + t + 4];
            }
#pragma unroll
            for (int mt = 0; mt < 4; mt++) {
                int mr = wm * 32 + mt * 8 + g;
                b[mt][0] = ks[mr * 36 + kk * 8 + t];
                b[mt][1] = ks[mr * 36 + kk * 8 + t + 4];
            }
#pragma unroll
            for (int nt = 0; nt < 2; nt++)
#pragma unroll
                for (int mt = 0; mt < 4; mt++)
                    mma8(sacc[nt][mt], a[nt][0], a[nt][1], a[nt][2], a[nt][3],
                         b[mt][0], b[mt][1]);
        }

        // --- e = exp(exp(s-B1)*is1 + atten - B2) -> es; sum2 partials ---
#pragma unroll
        for (int nt = 0; nt < 2; nt++)
#pragma unroll
            for (int mt = 0; mt < 4; mt++) {
                float4 c = sacc[nt][mt];
                int rl = wn * 32 + nt * 16 + g;
                int ml = wm * 32 + mt * 8 + 2 * t;
                size_t gb = ((size_t)(d * Nn + gn0 + rl)) * Nn + m0 + ml;
                float2 a0 = *(const float2*)(atten + gb);
                float2 a1 = *(const float2*)(atten + gb + (size_t)8 * Nn);
                float i0 = is1[rl], i1 = is1[rl + 8];
                float e0 = __expf(fmaf(__expf(c.x - B1), i0, a0.x) - B2);
                float e1 = __expf(fmaf(__expf(c.y - B1), i0, a0.y) - B2);
                float e2 = __expf(fmaf(__expf(c.z - B1), i1, a1.x) - B2);
                float e3 = __expf(fmaf(__expf(c.w - B1), i1, a1.y) - B2);
                part2[nt][0] += e0 + e1;
                part2[nt][1] += e2 + e3;
                es[rl * 68 + ml]           = cvt_tf32(e0);
                es[rl * 68 + ml + 1]       = cvt_tf32(e1);
                es[(rl + 8) * 68 + ml]     = cvt_tf32(e2);
                es[(rl + 8) * 68 + ml + 1] = cvt_tf32(e3);
            }
        __syncthreads();

        // --- ev mma: 128n x 64c, warp tile 32n x 32c, k=64m ---
#pragma unroll
        for (int kk = 0; kk < 8; kk++) {
            uint32_t a[2][4], b[4][2];
#pragma unroll
            for (int nt = 0; nt < 2; nt++) {
                int r = wn * 32 + nt * 16 + g;
                a[nt][0] = es[r * 68 + kk * 8 + t];
                a[nt][1] = es[(r + 8) * 68 + kk * 8 + t];
                a[nt][2] = es[r * 68 + kk * 8 + t + 4];
                a[nt][3] = es[(r + 8) * 68 + kk * 8 + t + 4];
            }
#pragma unroll
            for (int ct = 0; ct < 4; ct++) {
                int cr = wm * 32 + ct * 8 + g;
                b[ct][0] = vs[cr * 68 + kk * 8 + t];
                b[ct][1] = vs[cr * 68 + kk * 8 + t + 4];
            }
#pragma unroll
            for (int nt = 0; nt < 2; nt++)
#pragma unroll
                for (int ct = 0; ct < 4; ct++)
                    mma8(acc[nt][ct], a[nt][0], a[nt][1], a[nt][2], a[nt][3],
                         b[ct][0], b[ct][1]);
        }
    }

#pragma unroll
    for (int o = 1; o < 4; o <<= 1) {
#pragma unroll
        for (int nt = 0; nt < 2; nt++) {
            part2[nt][0] += __shfl_xor_sync(0xffffffffu, part2[nt][0], o);
            part2[nt][1] += __shfl_xor_sync(0xffffffffu, part2[nt][1], o);
        }
    }
    if (t == 0) {
#pragma unroll
        for (int nt = 0; nt < 2; nt++) {
            s2w[wm * 128 + wn * 32 + nt * 16 + g]     = part2[nt][0];
            s2w[wm * 128 + wn * 32 + nt * 16 + 8 + g] = part2[nt][1];
        }
    }
    __syncthreads();
    if (tid < 128)
        g_s2p[(gz * Dn + d) * Nn + gn0 + tid] = s2w[tid] + s2w[128 + tid];

#pragma unroll
    for (int nt = 0; nt < 2; nt++)
#pragma unroll
        for (int ct = 0; ct < 4; ct++) {
            float4 c = acc[nt][ct];
            int row = gn0 + wn * 32 + nt * 16 + g;
            int col = wm * 32 + ct * 8 + 2 * t;
            size_t b = ((size_t)((gz * Dn + d) * Nn) + row) * Cn + col;
            *(float2*)(g_part + b)          = make_float2(c.x, c.y);
            *(float2*)(g_part + b + 8 * Cn) = make_float2(c.z, c.w);
        }
}

// ========================= K4: reduce partials + normalize + residual =========================
__global__ __launch_bounds__(256) void epilogue(
    const float* __restrict__ x, const float* __restrict__ gamma,
    float* __restrict__ out)
{
    __shared__ float tb[32][33];
    __shared__ float inv[32];
    const int n0 = blockIdx.x * 32, c0 = blockIdx.y * 32, d = blockIdx.z;
    const int i = threadIdx.x & 31, j = threadIdx.x >> 5;
    const float g = gamma[0];

    if (threadIdx.x < 32) {
        float s = 0.f;
#pragma unroll
        for (int p = 0; p < SPL; p++) s += g_s2p[(p * Dn + d) * Nn + n0 + threadIdx.x];
        inv[threadIdx.x] = g / s;
    }
#pragma unroll
    for (int r = 0; r < 32; r += 8) {
        size_t base = ((size_t)(d * Nn) + n0 + j + r) * Cn + c0 + i;
        float v = 0.f;
#pragma unroll
        for (int p = 0; p < SPL; p++) v += g_part[(size_t)p * Dn * Nn * Cn + base];
        tb[j + r][i] = v;
    }
    __syncthreads();
#pragma unroll
    for (int r = 0; r < 32; r += 8) {
        size_t idx = ((size_t)(d * Cn + c0 + j + r)) * Nn + n0 + i;
        out[idx] = fmaf(tb[i][j + r], inv[i], x[idx]);
    }
}

// ============================================================================
extern "C" void kernel_launch(void* const* d_in, const int* in_sizes, int n_in,
                              void* d_out, int out_size)
{
    const float* x   = (const float*)d_in[0];
    const float* att = (const float*)d_in[1];
    const float* qw  = (const float*)d_in[2];
    const float* qb  = (const float*)d_in[3];
    const float* kw  = (const float*)d_in[4];
    const float* kb  = (const float*)d_in[5];
    const float* gm  = (const float*)d_in[6];
    float* out = (float*)d_out;

    static int smem_set = 0;
    const int dyn = (128 * 36 + 64 * 36 + 128 * 68 + 64 * 68 + 128 + 256) * 4;
    if (!smem_set) {
        cudaFuncSetAttribute(attn_v, cudaFuncAttributeMaxDynamicSharedMemorySize, dyn);
        smem_set = 1;
    }

    zero_qk <<<Dn * Nn * QKn / 4 / 256, 256>>>();
    conv_qk <<<dim3(Hn, Dn, 4), 256>>>(x, qw, qb, kw, kb);
    qk_sums <<<dim3(Nn / 64, Dn, SPL), 256>>>();
    attn_v  <<<dim3(Nn / 128, Dn, SPL), 256, dyn>>>(x, att);
    epilogue<<<dim3(Nn / 32, Cn / 32, Dn), 256>>>(x, gm, out);
}

// round 16
// speedup vs baseline: 1.2681x; 1.0425x over previous
#include <cuda_runtime.h>
#include <cstdint>

#define Dn 4
#define Cn 64
#define Hn 64
#define Wn 64
#define Nn 4096
#define QKn 32
#define B1 20.0f
#define B2 8.0f
#define SPL 4
#define MCH (Nn / SPL)
#define SPL3 8
#define MCH3 (Nn / SPL3)

__device__ __align__(16) float g_qt[Dn * Nn * QKn];   // q: [d][n][32]
__device__ __align__(16) float g_kt[Dn * Nn * QKn];   // k: [d][m][32]
__device__ __align__(16) float g_part[(size_t)SPL3 * Dn * Nn * Cn];
__device__ float g_sump[SPL * Dn * Nn];
__device__ float g_s2p [SPL3 * Dn * Nn];

__device__ __forceinline__ uint32_t cvt_tf32(float f) {
    uint32_t u;
    asm("cvt.rna.tf32.f32 %0, %1;" : "=r"(u) : "f"(f));
    return u;
}
__device__ __forceinline__ void mma8(float4& d,
    uint32_t a0, uint32_t a1, uint32_t a2, uint32_t a3,
    uint32_t b0, uint32_t b1)
{
    asm("mma.sync.aligned.m16n8k8.row.col.f32.tf32.tf32.f32 "
        "{%0,%1,%2,%3},{%4,%5,%6,%7},{%8,%9},{%0,%1,%2,%3};"
        : "+f"(d.x), "+f"(d.y), "+f"(d.z), "+f"(d.w)
        : "r"(a0), "r"(a1), "r"(a2), "r"(a3), "r"(b0), "r"(b1));
}

// ========================= K0: zero q/k accumulators =========================
__global__ __launch_bounds__(256) void zero_qk()
{
    int i = blockIdx.x * 256 + threadIdx.x;
    ((float4*)g_qt)[i] = make_float4(0.f, 0.f, 0.f, 0.f);
    ((float4*)g_kt)[i] = make_float4(0.f, 0.f, 0.f, 0.f);
}

// ========================= K1: conv3x3 -> q^T, k^T (R15 proven) =========================
__global__ __launch_bounds__(256) void conv_qk(
    const float* __restrict__ x,
    const float* __restrict__ qw, const float* __restrict__ qb,
    const float* __restrict__ kw, const float* __restrict__ kb)
{
    __shared__ float xs[3][16][72];
    __shared__ float wsm[16][9][32];
    const int h = blockIdx.x, d = blockIdx.y;
    const int proj = blockIdx.z >> 1, ichalf = blockIdx.z & 1;
    const int tid = threadIdx.x, oc = tid & 31, wg = tid >> 5;
    const float* wsrc = proj ? kw : qw;
    float acc[8];
    float bia = (ichalf == 0) ? (proj ? kb[oc] : qb[oc]) : 0.f;
#pragma unroll
    for (int j = 0; j < 8; j++) acc[j] = bia;

    for (int ch = 0; ch < 2; ch++) {
        const int chunk = ichalf * 2 + ch;
        for (int i = tid; i < 16 * 64; i += 256) {
            int icl = i >> 6, w = i & 63;
            const float* xp = x + ((size_t)(d * Cn + chunk * 16 + icl)) * (Hn * Wn);
#pragma unroll
            for (int dy = 0; dy < 3; dy++) {
                int hh = h + dy - 1;
                xs[dy][icl][w + 1] = (hh >= 0 && hh < Hn) ? xp[hh * Wn + w] : 0.f;
            }
            if (w == 0)
#pragma unroll
                for (int dy = 0; dy < 3; dy++) { xs[dy][icl][0] = 0.f; xs[dy][icl][65] = 0.f; }
        }
        for (int i = tid; i < 16 * 9 * 32; i += 256) {
            int icl = i / 288, rem = i % 288;
            wsm[icl][rem >> 5][rem & 31] = wsrc[((rem & 31) * Cn + chunk * 16 + icl) * 9 + (rem >> 5)];
        }
        __syncthreads();
        for (int icl = 0; icl < 16; icl++) {
#pragma unroll
            for (int dy = 0; dy < 3; dy++) {
                float4 x0 = *(const float4*)&xs[dy][icl][wg * 8];
                float4 x1 = *(const float4*)&xs[dy][icl][wg * 8 + 4];
                float2 x2 = *(const float2*)&xs[dy][icl][wg * 8 + 8];
                float xv[10] = {x0.x, x0.y, x0.z, x0.w, x1.x, x1.y, x1.z, x1.w, x2.x, x2.y};
#pragma unroll
                for (int dx = 0; dx < 3; dx++) {
                    float wv = wsm[icl][dy * 3 + dx][oc];
#pragma unroll
                    for (int j = 0; j < 8; j++) acc[j] = fmaf(wv, xv[dx + j], acc[j]);
                }
            }
        }
        __syncthreads();
    }
    const int n = h * Wn + wg * 8;
    float* dst = proj ? g_kt : g_qt;
#pragma unroll
    for (int j = 0; j < 8; j++)
        atomicAdd(&dst[((size_t)(d * Nn + n + j)) * QKn + oc], acc[j]);
}

// ========================= K2: softmax1 sums only (R13 proven, SPL=4) =========================
__global__ __launch_bounds__(256) void qk_sums()
{
    __shared__ uint32_t qs[64 * 36];
    __shared__ uint32_t ks[128 * 36];
    __shared__ float s1w[4][64];

    const int d = blockIdx.y, gn0 = blockIdx.x * 64, gz = blockIdx.z;
    const int tid = threadIdx.x, lane = tid & 31, warp = tid >> 5;
    const int wn = warp >> 2, wm = warp & 3;
    const int g = lane >> 2, t = lane & 3;

    {
        int n = tid >> 2, cq = (tid & 3) * 8;
        const float* qp = g_qt + ((size_t)(d * Nn + gn0 + n)) * QKn + cq;
#pragma unroll
        for (int e = 0; e < 8; e++) qs[n * 36 + cq + e] = cvt_tf32(qp[e]);
    }
    __syncthreads();

    uint32_t af[2][4][4];
#pragma unroll
    for (int nt = 0; nt < 2; nt++)
#pragma unroll
        for (int kk = 0; kk < 4; kk++) {
            int r = wn * 32 + nt * 16 + g;
            af[nt][kk][0] = qs[r * 36 + kk * 8 + t];
            af[nt][kk][1] = qs[(r + 8) * 36 + kk * 8 + t];
            af[nt][kk][2] = qs[r * 36 + kk * 8 + t + 4];
            af[nt][kk][3] = qs[(r + 8) * 36 + kk * 8 + t + 4];
        }

    float part[4] = {0.f, 0.f, 0.f, 0.f};

    for (int m0 = gz * MCH; m0 < (gz + 1) * MCH; m0 += 128) {
        __syncthreads();
#pragma unroll
        for (int it = 0; it < 2; it++) {
            int gg = tid + 256 * it;
            int m = gg >> 2, cq = (gg & 3) * 8;
            const float* kp = g_kt + ((size_t)(d * Nn + m0 + m)) * QKn + cq;
#pragma unroll
            for (int e = 0; e < 8; e++) ks[m * 36 + cq + e] = cvt_tf32(kp[e]);
        }
        __syncthreads();

        float4 acc[2][4];
#pragma unroll
        for (int nt = 0; nt < 2; nt++)
#pragma unroll
            for (int mt = 0; mt < 4; mt++) acc[nt][mt] = make_float4(0.f, 0.f, 0.f, 0.f);

#pragma unroll
        for (int kk = 0; kk < 4; kk++) {
            uint32_t bf[4][2];
#pragma unroll
            for (int mt = 0; mt < 4; mt++) {
                int mr = wm * 32 + mt * 8 + g;
                bf[mt][0] = ks[mr * 36 + kk * 8 + t];
                bf[mt][1] = ks[mr * 36 + kk * 8 + t + 4];
            }
#pragma unroll
            for (int nt = 0; nt < 2; nt++)
#pragma unroll
                for (int mt = 0; mt < 4; mt++)
                    mma8(acc[nt][mt], af[nt][kk][0], af[nt][kk][1], af[nt][kk][2], af[nt][kk][3],
                         bf[mt][0], bf[mt][1]);
        }

#pragma unroll
        for (int nt = 0; nt < 2; nt++)
#pragma unroll
            for (int mt = 0; mt < 4; mt++) {
                float4 c = acc[nt][mt];
                part[nt * 2 + 0] += __expf(c.x - B1) + __expf(c.y - B1);
                part[nt * 2 + 1] += __expf(c.z - B1) + __expf(c.w - B1);
            }
    }

#pragma unroll
    for (int o = 1; o < 4; o <<= 1)
#pragma unroll
        for (int i = 0; i < 4; i++) part[i] += __shfl_xor_sync(0xffffffffu, part[i], o);
    if (t == 0)
#pragma unroll
        for (int i = 0; i < 4; i++)
            s1w[wm][wn * 32 + (i >> 1) * 16 + (i & 1) * 8 + g] = part[i];
    __syncthreads();
    if (tid < 64)
        g_sump[(gz * Dn + d) * Nn + gn0 + tid] =
            s1w[0][tid] + s1w[1][tid] + s1w[2][tid] + s1w[3][tid];
}

// ========================= K3: fused scores + double softmax + attn@V (SPL3=8) =========================
__global__ __launch_bounds__(256) void attn_v(
    const float* __restrict__ x, const float* __restrict__ atten)
{
    extern __shared__ float sh[];
    uint32_t* qs = (uint32_t*)sh;               // [128][36]
    uint32_t* ks = qs + 128 * 36;               // [64][36]
    uint32_t* es = ks + 64 * 36;                // [128][68]
    uint32_t* vs = es + 128 * 68;               // [64][68]
    float* is1 = (float*)(vs + 64 * 68);        // [128]
    float* s2w = is1 + 128;                     // [2][128]

    const int d = blockIdx.y, gn0 = blockIdx.x * 128, gz = blockIdx.z;
    const int tid = threadIdx.x, lane = tid & 31, warp = tid >> 5;
    const int wn = warp >> 1, wm = warp & 1;
    const int g = lane >> 2, t = lane & 3;

    if (tid < 128) {
        float s = 0.f;
#pragma unroll
        for (int p = 0; p < SPL; p++) s += g_sump[(p * Dn + d) * Nn + gn0 + tid];
        is1[tid] = 1.0f / s;
    }
#pragma unroll
    for (int it = 0; it < 2; it++) {
        int gg = tid + 256 * it;
        int n = gg >> 2, cq = (gg & 3) * 8;
        const float* qp = g_qt + ((size_t)(d * Nn + gn0 + n)) * QKn + cq;
#pragma unroll
        for (int e = 0; e < 8; e++) qs[n * 36 + cq + e] = cvt_tf32(qp[e]);
    }

    float4 acc[2][4];
#pragma unroll
    for (int nt = 0; nt < 2; nt++)
#pragma unroll
        for (int ct = 0; ct < 4; ct++) acc[nt][ct] = make_float4(0.f, 0.f, 0.f, 0.f);
    float part2[2][2] = {{0.f, 0.f}, {0.f, 0.f}};

    for (int m0 = gz * MCH3; m0 < (gz + 1) * MCH3; m0 += 64) {
        __syncthreads();
        {
            int m = tid >> 2, cq = (tid & 3) * 8;
            const float* kp = g_kt + ((size_t)(d * Nn + m0 + m)) * QKn + cq;
#pragma unroll
            for (int e = 0; e < 8; e++) ks[m * 36 + cq + e] = cvt_tf32(kp[e]);
        }
#pragma unroll
        for (int it = 0; it < 4; it++) {
            int gg = tid + 256 * it;
            int c = gg >> 4, mq = gg & 15;
            float4 v4 = *(const float4*)(x + ((size_t)(d * Cn + c)) * Nn + m0 + mq * 4);
            *(uint4*)&vs[c * 68 + mq * 4] =
                make_uint4(cvt_tf32(v4.x), cvt_tf32(v4.y), cvt_tf32(v4.z), cvt_tf32(v4.w));
        }
        __syncthreads();

        // --- score mma: 128n x 64m, warp tile 32n x 32m ---
        float4 sacc[2][4];
#pragma unroll
        for (int nt = 0; nt < 2; nt++)
#pragma unroll
            for (int mt = 0; mt < 4; mt++) sacc[nt][mt] = make_float4(0.f, 0.f, 0.f, 0.f);
#pragma unroll
        for (int kk = 0; kk < 4; kk++) {
            uint32_t a[2][4], b[4][2];
#pragma unroll
            for (int nt = 0; nt < 2; nt++) {
                int r = wn * 32 + nt * 16 + g;
                a[nt][0] = qs[r * 36 + kk * 8 + t];
                a[nt][1] = qs[(r + 8) * 36 + kk * 8 + t];
                a[nt][2] = qs[r * 36 + kk * 8 + t + 4];
                a[nt][3] = qs[(r + 8) * 36 + kk * 8 + t + 4];
            }
#pragma unroll
            for (int mt = 0; mt < 4; mt++) {
                int mr = wm * 32 + mt * 8 + g;
                b[mt][0] = ks[mr * 36 + kk * 8 + t];
                b[mt][1] = ks[mr * 36 + kk * 8 + t + 4];
            }
#pragma unroll
            for (int nt = 0; nt < 2; nt++)
#pragma unroll
                for (int mt = 0; mt < 4; mt++)
                    mma8(sacc[nt][mt], a[nt][0], a[nt][1], a[nt][2], a[nt][3],
                         b[mt][0], b[mt][1]);
        }

        // --- e = exp(exp(s-B1)*is1 + atten - B2) -> es; sum2 partials ---
#pragma unroll
        for (int nt = 0; nt < 2; nt++)
#pragma unroll
            for (int mt = 0; mt < 4; mt++) {
                float4 c = sacc[nt][mt];
                int rl = wn * 32 + nt * 16 + g;
                int ml = wm * 32 + mt * 8 + 2 * t;
                size_t gb = ((size_t)(d * Nn + gn0 + rl)) * Nn + m0 + ml;
                float2 a0 = *(const float2*)(atten + gb);
                float2 a1 = *(const float2*)(atten + gb + (size_t)8 * Nn);
                float i0 = is1[rl], i1 = is1[rl + 8];
                float e0 = __expf(fmaf(__expf(c.x - B1), i0, a0.x) - B2);
                float e1 = __expf(fmaf(__expf(c.y - B1), i0, a0.y) - B2);
                float e2 = __expf(fmaf(__expf(c.z - B1), i1, a1.x) - B2);
                float e3 = __expf(fmaf(__expf(c.w - B1), i1, a1.y) - B2);
                part2[nt][0] += e0 + e1;
                part2[nt][1] += e2 + e3;
                es[rl * 68 + ml]           = cvt_tf32(e0);
                es[rl * 68 + ml + 1]       = cvt_tf32(e1);
                es[(rl + 8) * 68 + ml]     = cvt_tf32(e2);
                es[(rl + 8) * 68 + ml + 1] = cvt_tf32(e3);
            }
        __syncthreads();

        // --- ev mma: 128n x 64c, warp tile 32n x 32c, k=64m ---
#pragma unroll
        for (int kk = 0; kk < 8; kk++) {
            uint32_t a[2][4], b[4][2];
#pragma unroll
            for (int nt = 0; nt < 2; nt++) {
                int r = wn * 32 + nt * 16 + g;
                a[nt][0] = es[r * 68 + kk * 8 + t];
                a[nt][1] = es[(r + 8) * 68 + kk * 8 + t];
                a[nt][2] = es[r * 68 + kk * 8 + t + 4];
                a[nt][3] = es[(r + 8) * 68 + kk * 8 + t + 4];
            }
#pragma unroll
            for (int ct = 0; ct < 4; ct++) {
                int cr = wm * 32 + ct * 8 + g;
                b[ct][0] = vs[cr * 68 + kk * 8 + t];
                b[ct][1] = vs[cr * 68 + kk * 8 + t + 4];
            }
#pragma unroll
            for (int nt = 0; nt < 2; nt++)
#pragma unroll
                for (int ct = 0; ct < 4; ct++)
                    mma8(acc[nt][ct], a[nt][0], a[nt][1], a[nt][2], a[nt][3],
                         b[ct][0], b[ct][1]);
        }
    }

#pragma unroll
    for (int o = 1; o < 4; o <<= 1) {
#pragma unroll
        for (int nt = 0; nt < 2; nt++) {
            part2[nt][0] += __shfl_xor_sync(0xffffffffu, part2[nt][0], o);
            part2[nt][1] += __shfl_xor_sync(0xffffffffu, part2[nt][1], o);
        }
    }
    if (t == 0) {
#pragma unroll
        for (int nt = 0; nt < 2; nt++) {
            s2w[wm * 128 + wn * 32 + nt * 16 + g]     = part2[nt][0];
            s2w[wm * 128 + wn * 32 + nt * 16 + 8 + g] = part2[nt][1];
        }
    }
    __syncthreads();
    if (tid < 128)
        g_s2p[(gz * Dn + d) * Nn + gn0 + tid] = s2w[tid] + s2w[128 + tid];

#pragma unroll
    for (int nt = 0; nt < 2; nt++)
#pragma unroll
        for (int ct = 0; ct < 4; ct++) {
            float4 c = acc[nt][ct];
            int row = gn0 + wn * 32 + nt * 16 + g;
            int col = wm * 32 + ct * 8 + 2 * t;
            size_t b = ((size_t)((gz * Dn + d) * Nn) + row) * Cn + col;
            *(float2*)(g_part + b)          = make_float2(c.x, c.y);
            *(float2*)(g_part + b + 8 * Cn) = make_float2(c.z, c.w);
        }
}

// ========================= K4: reduce partials + normalize + residual =========================
__global__ __launch_bounds__(256) void epilogue(
    const float* __restrict__ x, const float* __restrict__ gamma,
    float* __restrict__ out)
{
    __shared__ float tb[32][33];
    __shared__ float inv[32];
    const int n0 = blockIdx.x * 32, c0 = blockIdx.y * 32, d = blockIdx.z;
    const int i = threadIdx.x & 31, j = threadIdx.x >> 5;
    const float g = gamma[0];

    if (threadIdx.x < 32) {
        float s = 0.f;
#pragma unroll
        for (int p = 0; p < SPL3; p++) s += g_s2p[(p * Dn + d) * Nn + n0 + threadIdx.x];
        inv[threadIdx.x] = g / s;
    }
#pragma unroll
    for (int r = 0; r < 32; r += 8) {
        size_t base = ((size_t)(d * Nn) + n0 + j + r) * Cn + c0 + i;
        float v = 0.f;
#pragma unroll
        for (int p = 0; p < SPL3; p++) v += g_part[(size_t)p * Dn * Nn * Cn + base];
        tb[j + r][i] = v;
    }
    __syncthreads();
#pragma unroll
    for (int r = 0; r < 32; r += 8) {
        size_t idx = ((size_t)(d * Cn + c0 + j + r)) * Nn + n0 + i;
        out[idx] = fmaf(tb[i][j + r], inv[i], x[idx]);
    }
}

// ============================================================================
extern "C" void kernel_launch(void* const* d_in, const int* in_sizes, int n_in,
                              void* d_out, int out_size)
{
    const float* x   = (const float*)d_in[0];
    const float* att = (const float*)d_in[1];
    const float* qw  = (const float*)d_in[2];
    const float* qb  = (const float*)d_in[3];
    const float* kw  = (const float*)d_in[4];
    const float* kb  = (const float*)d_in[5];
    const float* gm  = (const float*)d_in[6];
    float* out = (float*)d_out;

    static int smem_set = 0;
    const int dyn = (128 * 36 + 64 * 36 + 128 * 68 + 64 * 68 + 128 + 256) * 4;
    if (!smem_set) {
        cudaFuncSetAttribute(attn_v, cudaFuncAttributeMaxDynamicSharedMemorySize, dyn);
        smem_set = 1;
    }

    zero_qk <<<Dn * Nn * QKn / 4 / 256, 256>>>();
    conv_qk <<<dim3(Hn, Dn, 4), 256>>>(x, qw, qb, kw, kb);
    qk_sums <<<dim3(Nn / 64, Dn, SPL), 256>>>();
    attn_v  <<<dim3(Nn / 128, Dn, SPL3), 256, dyn>>>(x, att);
    epilogue<<<dim3(Nn / 32, Cn / 32, Dn), 256>>>(x, gm, out);
}